// round 5
// baseline (speedup 1.0000x reference)
#include <cuda_runtime.h>
#include <cstdint>

#define NN 100000
#define EE 1600000
#define RR 6
#define CIN 8
#define COUT 16
#define CHUNK 1024

__device__ int   g_counts[NN];
__device__ int   g_rowstart[NN + 1];
__device__ int   g_cursor[NN];
__device__ int   g_perm[EE];
__device__ int   g_bsum[256];
__device__ int   g_boff[256];
__device__ float2 g_phase[CIN * COUT];
__device__ int   g_is64;

// ---------------------------------------------------------------------------
// K0: detect whether supp_edges is int64 or int32.
// If int64 (values < 2^31), every odd 32-bit word (high half) is 0.
// If int32, odd words are node indices; P(256 sampled all zero) ~ 0.
__global__ void k_detect(const unsigned int* __restrict__ words) {
    if (threadIdx.x == 0 && blockIdx.x == 0) {
        int any = 0;
        for (int i = 1; i < 512; i += 2) any |= (words[i] != 0u);
        g_is64 = any ? 0 : 1;
    }
}

// K1: zero histogram + precompute phase = (cos, sin)(offset)
__global__ void k_init(const float* __restrict__ offset, int n) {
    int i = blockIdx.x * blockDim.x + threadIdx.x;
    if (i < CIN * COUT) {
        float o = offset[i];
        g_phase[i] = make_float2(cosf(o), sinf(o));
    }
    if (i < n) g_counts[i] = 0;
}

__device__ __forceinline__ int load_dst(const char* edges, int e, int is64) {
    if (is64) return (int)((const long long*)edges)[2 * (long long)e + 1];
    return ((const int*)edges)[2 * e + 1];
}
__device__ __forceinline__ int load_src(const char* edges, int e, int is64) {
    if (is64) return (int)((const long long*)edges)[2 * (long long)e];
    return ((const int*)edges)[2 * e];
}

// K2: histogram of destination degrees
__global__ void k_hist(const char* __restrict__ edges, int E) {
    int e = blockIdx.x * blockDim.x + threadIdx.x;
    if (e >= E) return;
    int dst = load_dst(edges, e, g_is64);
    atomicAdd(&g_counts[dst], 1);
}

// K3a: per-block scan of CHUNK=1024 counts (256 threads x 4 elems)
__global__ void k_scan1(int n) {
    __shared__ int sh[256];
    int b = blockIdx.x, t = threadIdx.x;
    int base = b * CHUNK + t * 4;
    int v0 = 0, v1 = 0, v2 = 0, v3 = 0;
    if (base + 0 < n) v0 = g_counts[base + 0];
    if (base + 1 < n) v1 = g_counts[base + 1];
    if (base + 2 < n) v2 = g_counts[base + 2];
    if (base + 3 < n) v3 = g_counts[base + 3];
    int tot = v0 + v1 + v2 + v3;
    sh[t] = tot;
    __syncthreads();
    for (int off = 1; off < 256; off <<= 1) {
        int val = 0;
        if (t >= off) val = sh[t - off];
        __syncthreads();
        sh[t] += val;
        __syncthreads();
    }
    int run = sh[t] - tot;  // exclusive within block
    if (base + 0 < n) { g_rowstart[base + 0] = run; run += v0; }
    if (base + 1 < n) { g_rowstart[base + 1] = run; run += v1; }
    if (base + 2 < n) { g_rowstart[base + 2] = run; run += v2; }
    if (base + 3 < n) { g_rowstart[base + 3] = run; run += v3; }
    if (t == 255) g_bsum[b] = sh[255];
}

// K3b: scan the (<=128) block sums
__global__ void k_scan2(int nb) {
    __shared__ int sh[128];
    int t = threadIdx.x;
    int v = (t < nb) ? g_bsum[t] : 0;
    sh[t] = v;
    __syncthreads();
    for (int off = 1; off < 128; off <<= 1) {
        int val = 0;
        if (t >= off) val = sh[t - off];
        __syncthreads();
        sh[t] += val;
        __syncthreads();
    }
    if (t < nb) g_boff[t] = sh[t] - v;  // exclusive
}

// K3c: add block offsets, init cursor, terminate rowstart
__global__ void k_scan3(int n, int E) {
    int i = blockIdx.x * blockDim.x + threadIdx.x;
    if (i < n) {
        int v = g_rowstart[i] + g_boff[i >> 10];
        g_rowstart[i] = v;
        g_cursor[i] = v;
    }
    if (i == 0) g_rowstart[n] = E;
}

// K4: scatter edge ids into dst-sorted order
__global__ void k_scatter(const char* __restrict__ edges, int E) {
    int e = blockIdx.x * blockDim.x + threadIdx.x;
    if (e >= E) return;
    int dst = load_dst(edges, e, g_is64);
    int pos = atomicAdd(&g_cursor[dst], 1);
    g_perm[pos] = e;
}

// K5: per-node aggregation (registers) + factored complex contraction + gate
__global__ void __launch_bounds__(128)
k_node(const float* __restrict__ x, const char* __restrict__ edges,
       const float* __restrict__ sten, const float* __restrict__ weight,
       const float* __restrict__ bias, float* __restrict__ out, int n_nodes) {
    __shared__ float  sw[RR * CIN * COUT];   // 768 floats
    __shared__ float2 sp[CIN * COUT];        // 128 float2
    __shared__ float  sb[COUT];
    int t = threadIdx.x;
    for (int i = t; i < RR * CIN * COUT; i += 128) sw[i] = weight[i];
    sp[t] = g_phase[t];                      // t in [0,128)
    if (t < COUT) sb[t] = bias[t];
    __syncthreads();

    int n = blockIdx.x * 128 + t;
    if (n >= n_nodes) return;

    float ar[RR * CIN], ai[RR * CIN];
#pragma unroll
    for (int k = 0; k < RR * CIN; k++) { ar[k] = 0.f; ai[k] = 0.f; }

    int beg = g_rowstart[n];
    int end = g_rowstart[n + 1];
    int is64 = g_is64;

    for (int i = beg; i < end; i++) {
        int e = g_perm[i];
        int src;
        if (is64) {
            longlong2 v = ((const longlong2*)edges)[e];
            src = (int)v.x;
        } else {
            int2 v = ((const int2*)edges)[e];
            src = v.x;
        }
        const float4* s4 = (const float4*)(sten + (size_t)e * 12);
        float4 s0 = s4[0], s1 = s4[1], s2 = s4[2];
        const float4* x4 = (const float4*)(x + (size_t)src * 8);
        float4 xa = x4[0], xb = x4[1];

        float sr[RR] = {s0.x, s0.z, s1.x, s1.z, s2.x, s2.z};
        float si[RR] = {s0.y, s0.w, s1.y, s1.w, s2.y, s2.w};
        float xv[CIN] = {xa.x, xa.y, xa.z, xa.w, xb.x, xb.y, xb.z, xb.w};
#pragma unroll
        for (int r = 0; r < RR; r++) {
#pragma unroll
            for (int c = 0; c < CIN; c++) {
                ar[r * CIN + c] += sr[r] * xv[c];
                ai[r * CIN + c] += si[r] * xv[c];
            }
        }
    }

    // y[o] = sum_c phase[c,o] * (sum_r agg[r,c] * w[r,c,o]); gate by magnitude
    float2* o2 = (float2*)out;
#pragma unroll 4
    for (int o = 0; o < COUT; o++) {
        float yr = 0.f, yi = 0.f;
#pragma unroll
        for (int c = 0; c < CIN; c++) {
            float tr = 0.f, ti = 0.f;
#pragma unroll
            for (int r = 0; r < RR; r++) {
                float w = sw[(r * CIN + c) * COUT + o];
                tr += ar[r * CIN + c] * w;
                ti += ai[r * CIN + c] * w;
            }
            float2 ph = sp[c * COUT + o];
            yr += tr * ph.x - ti * ph.y;
            yi += tr * ph.y + ti * ph.x;
        }
        float mag = sqrtf(yr * yr + yi * yi);
        float sc = fmaxf(mag + sb[o], 0.f) / (mag + 1e-8f);
        o2[(size_t)n * COUT + o] = make_float2(yr * sc, yi * sc);
    }
}

extern "C" void kernel_launch(void* const* d_in, const int* in_sizes, int n_in,
                              void* d_out, int out_size) {
    const float* x      = (const float*)d_in[0];
    const char*  edges  = (const char*)d_in[1];
    const float* sten   = (const float*)d_in[2];
    const float* weight = (const float*)d_in[3];
    const float* offset = (const float*)d_in[4];
    const float* bias   = (const float*)d_in[5];
    float*       out    = (float*)d_out;

    int E = in_sizes[1] / 2;
    int n = in_sizes[0] / CIN;

    k_detect<<<1, 32>>>((const unsigned int*)edges);
    k_init<<<(n + 255) / 256, 256>>>(offset, n);
    k_hist<<<(E + 255) / 256, 256>>>(edges, E);
    int nb = (n + CHUNK - 1) / CHUNK;
    k_scan1<<<nb, 256>>>(n);
    k_scan2<<<1, 128>>>(nb);
    k_scan3<<<(n + 255) / 256, 256>>>(n, E);
    k_scatter<<<(E + 255) / 256, 256>>>(edges, E);
    k_node<<<(n + 127) / 128, 128>>>(x, edges, sten, weight, bias, out, n);
}